// round 4
// baseline (speedup 1.0000x reference)
#include <cuda_runtime.h>
#include <cstddef>

typedef unsigned long long ULL;

#define EPSF 1e-5f
#define NB 8
#define HW 256
#define NODES 340      // 4 views * 5 T * 17 V
#define ST 20          // activation row stride (floats)

// ---- constant-memory parameter layout (floats) ----
#define CASP 0         // A_sp padded: 4*17 rows x 20  = 1360
#define CATM 1360      // A_tm padded: 2*5 rows x 8    = 80
#define CAVW 1440      // A_vw: 4x4                    = 16
#define CWG0 1456      // 7*18*16 [k][c][o], s1-folded = 2016
#define CWG1 3472      // 7*16*16                      = 1792
#define CWG2 5264      // 1792
#define CBG  7056      // 3*7*16, s1-folded            = 336
#define CB1  7392      // 336
#define CWT  7728      // 3*7*16*16 [l][k][c][o], s2-folded = 5376
#define CCI  13104     // 3*16: sum_k(bt*s2+b2)        = 48
#define CTOT 13152     // 52.6 KB

__constant__ float cP[CTOT];
__device__   float gS[CTOT];

// ---- packed-f32x2 helpers (Blackwell) ----
__device__ __forceinline__ ULL f2fma(ULL a, ULL b, ULL c){
  ULL d; asm("fma.rn.f32x2 %0,%1,%2,%3;" : "=l"(d) : "l"(a), "l"(b), "l"(c)); return d;
}
__device__ __forceinline__ ULL f2add(ULL a, ULL b){
  ULL d; asm("add.rn.f32x2 %0,%1,%2;" : "=l"(d) : "l"(a), "l"(b)); return d;
}
__device__ __forceinline__ ULL pkdup(float a){
  ULL d; asm("mov.b64 %0,{%1,%1};" : "=l"(d) : "f"(a), "f"(a)); return d;
}
__device__ __forceinline__ ULL pk(float a, float b){
  ULL d; asm("mov.b64 %0,{%1,%2};" : "=l"(d) : "f"(a), "f"(b)); return d;
}
__device__ __forceinline__ float2 up2(ULL a){
  float2 v; asm("mov.b64 {%0,%1},%2;" : "=f"(v.x), "=f"(v.y) : "l"(a)); return v;
}
__device__ __forceinline__ ULL lds2(const float* p){ return *reinterpret_cast<const ULL*>(p); }
__device__ __forceinline__ void sts2(float* p, ULL v){ *reinterpret_cast<ULL*>(p) = v; }
__device__ __forceinline__ ULL cld2(int idx){ return *reinterpret_cast<const ULL*>(cP + idx); }
__device__ __forceinline__ float4 cld4(int idx){ return *reinterpret_cast<const float4*>(cP + idx); }

// ---------------- prep: fold BN scales into weights, pad A, transpose ----------------
__global__ void prep_kernel(const float* __restrict__ A_sp, const float* __restrict__ A_tm,
                            const float* __restrict__ A_vw,
                            const float* __restrict__ Wg0, const float* __restrict__ bg0,
                            const float* __restrict__ Wg,  const float* __restrict__ bg,
                            const float* __restrict__ bn1g, const float* __restrict__ bn1b,
                            const float* __restrict__ Wt,  const float* __restrict__ bt,
                            const float* __restrict__ bn2g, const float* __restrict__ bn2b)
{
  const int t = threadIdx.x;
  const float inv = rsqrtf(1.f + EPSF);
  // A_sp padded rows of 20
  for (int i = t; i < 1360; i += 256){
    int k = i / 340, r = i % 340, u = r / 20, vp = r % 20;
    gS[CASP + i] = (vp < 17) ? A_sp[(k*17 + u)*17 + vp] : 0.f;
  }
  // A_tm padded rows of 8
  for (int i = t; i < 80; i += 256){
    int k = i / 40, r = i % 40, tt = r / 8, tp = r % 8;
    gS[CATM + i] = (tp < 5) ? A_tm[(k*5 + tt)*5 + tp] : 0.f;
  }
  for (int i = t; i < 16; i += 256) gS[CAVW + i] = A_vw[i];
  // Wg0: (7,16,18) [k][o][c] -> [k][c][o], * s1(layer0)
  for (int i = t; i < 2016; i += 256){
    int k = i / 288, r = i % 288, o = r / 18, c = r % 18;
    gS[CWG0 + (k*18 + c)*16 + o] = Wg0[i] * (bn1g[k*16 + o] * inv);
  }
  // Wg: (2,7,16,16) [l][k][o][c] -> per-layer [k][c][o], * s1(layer l+1)
  for (int i = t; i < 3584; i += 256){
    int l = i / 1792, r = i % 1792, k = r / 256, q = r % 256, o = q / 16, c = q % 16;
    gS[CWG1 + l*1792 + (k*16 + c)*16 + o] = Wg[i] * (bn1g[((l+1)*7 + k)*16 + o] * inv);
  }
  // bg (s1-folded) and b1
  for (int i = t; i < 336; i += 256){
    float bgv = (i < 112) ? bg0[i] : bg[i - 112];
    gS[CBG + i] = bgv * (bn1g[i] * inv);
    gS[CB1 + i] = bn1b[i];
  }
  // Wt: (3,7,16,16) [l][k][o][c] -> [l][k][c][o], * s2
  for (int i = t; i < 5376; i += 256){
    int l = i / 1792, r = i % 1792, k = r / 256, q = r % 256, o = q / 16, c = q % 16;
    gS[CWT + l*1792 + (k*16 + c)*16 + o] = Wt[i] * (bn2g[(l*7 + k)*16 + o] * inv);
  }
  // CI[l][o] = sum_k (bt*s2 + b2)
  for (int i = t; i < 48; i += 256){
    int l = i / 16, o = i % 16;
    float s = 0.f;
    for (int k = 0; k < 7; k++){
      int id = (l*7 + k)*16 + o;
      s += bt[id] * (bn2g[id] * inv) + bn2b[id];
    }
    gS[CCI + i] = s;
  }
}

// ---- phase A: conv1 (s1-folded weights from constant) -> y rows in sA ----
template<int CIN>
__device__ __forceinline__ void phaseA(int wb, int bb,
                                       const float (&xr0)[18], const float (&xr1)[18],
                                       float* sA, int nd0, int nd1, bool has2)
{
  ULL y0[8], y1[8];
  #pragma unroll
  for (int q = 0; q < 8; q++){ ULL b = cld2(bb + 2*q); y0[q] = b; y1[q] = b; }
  #pragma unroll
  for (int c = 0; c < CIN; c++){
    ULL xa = pkdup(xr0[c]), xb = pkdup(xr1[c]);
    #pragma unroll
    for (int q = 0; q < 8; q++){
      ULL w = cld2(wb + c*16 + 2*q);
      y0[q] = f2fma(w, xa, y0[q]);
      y1[q] = f2fma(w, xb, y1[q]);
    }
  }
  ULL* d0 = reinterpret_cast<ULL*>(sA + nd0*ST);
  #pragma unroll
  for (int q = 0; q < 8; q++) d0[q] = y0[q];
  if (has2){
    ULL* d1 = reinterpret_cast<ULL*>(sA + nd1*ST);
    #pragma unroll
    for (int q = 0; q < 8; q++) d1[q] = y1[q];
  }
}

// ---- phase C: conv2 (s2-folded) accumulated straight into acc ----
__device__ __forceinline__ void phaseC(int wb, const float* sA, int nd0, int nd1,
                                       ULL (&acc0)[8], ULL (&acc1)[8])
{
  float4 ra[4], rb[4];
  #pragma unroll
  for (int q = 0; q < 4; q++){
    ra[q] = *reinterpret_cast<const float4*>(sA + nd0*ST + 4*q);
    rb[q] = *reinterpret_cast<const float4*>(sA + nd1*ST + 4*q);
  }
  #pragma unroll
  for (int q4 = 0; q4 < 4; q4++){
    const float av[4] = {ra[q4].x, ra[q4].y, ra[q4].z, ra[q4].w};
    const float bv[4] = {rb[q4].x, rb[q4].y, rb[q4].z, rb[q4].w};
    #pragma unroll
    for (int s = 0; s < 4; s++){
      int c = q4*4 + s;
      ULL xa = pkdup(av[s]), xb = pkdup(bv[s]);
      #pragma unroll
      for (int q = 0; q < 8; q++){
        ULL w = cld2(wb + c*16 + 2*q);
        acc0[q] = f2fma(w, xa, acc0[q]);
        acc1[q] = f2fma(w, xb, acc1[q]);
      }
    }
  }
}

// ---- phase B spatial: per (group, ch-pair) slice, in-place A-mix + b1 + ReLU ----
__device__ __forceinline__ void phaseBsp(int L, int k, float* sA, int tid)
{
  if (tid >= 160) return;
  const int g = tid >> 3, cp = tid & 7;
  const int base = (g*17)*ST + 2*cp;
  ULL ys[20];
  #pragma unroll
  for (int v = 0; v < 17; v++) ys[v] = lds2(sA + base + v*ST);
  ys[17] = 0ULL; ys[18] = 0ULL; ys[19] = 0ULL;
  const ULL b1 = cld2(CB1 + (L*7 + k)*16 + 2*cp);
  const int ab = CASP + k*340;
  #pragma unroll
  for (int u = 0; u < 17; u++){
    ULL z = 0ULL;
    #pragma unroll
    for (int q = 0; q < 5; q++){
      float4 a = cld4(ab + u*20 + 4*q);
      z = f2fma(ys[4*q + 0], pkdup(a.x), z);
      z = f2fma(ys[4*q + 1], pkdup(a.y), z);
      z = f2fma(ys[4*q + 2], pkdup(a.z), z);
      z = f2fma(ys[4*q + 3], pkdup(a.w), z);
    }
    float2 f = up2(f2add(z, b1));
    sts2(sA + base + u*ST, pk(fmaxf(f.x, 0.f), fmaxf(f.y, 0.f)));
  }
}

// ---- phase B temporal ----
__device__ __forceinline__ void phaseBtm(int L, int k, float* sA, int tid)
{
  const int b1b = CB1 + (L*7 + k)*16;
  const int ab  = CATM + (k - 4)*40;
  for (int it = tid; it < 544; it += 192){
    int vw = it / 136; int r = it - vw*136; int v = r >> 3; int cp = r & 7;
    const int base = (vw*85 + v)*ST + 2*cp;   // node (vw*5+tp)*17+v, tp stride 17*ST
    ULL ys[5];
    #pragma unroll
    for (int tp = 0; tp < 5; tp++) ys[tp] = lds2(sA + base + tp*17*ST);
    const ULL b1 = cld2(b1b + 2*cp);
    #pragma unroll
    for (int t = 0; t < 5; t++){
      float4 a0 = cld4(ab + t*8);
      float  a4 = cP[ab + t*8 + 4];
      ULL z = 0ULL;
      z = f2fma(ys[0], pkdup(a0.x), z);
      z = f2fma(ys[1], pkdup(a0.y), z);
      z = f2fma(ys[2], pkdup(a0.z), z);
      z = f2fma(ys[3], pkdup(a0.w), z);
      z = f2fma(ys[4], pkdup(a4),   z);
      float2 f = up2(f2add(z, b1));
      sts2(sA + base + t*17*ST, pk(fmaxf(f.x, 0.f), fmaxf(f.y, 0.f)));
    }
  }
}

// ---- phase B views ----
__device__ __forceinline__ void phaseBvw(int L, float* sA, int tid)
{
  const int b1b = CB1 + (L*7 + 6)*16;
  for (int it = tid; it < 680; it += 192){
    int t = it / 136; int r = it - t*136; int v = r >> 3; int cp = r & 7;
    const int base = (t*17 + v)*ST + 2*cp;    // node (vw*85 + t*17 + v), vw stride 85*ST
    ULL ys[4];
    #pragma unroll
    for (int vw = 0; vw < 4; vw++) ys[vw] = lds2(sA + base + vw*85*ST);
    const ULL b1 = cld2(b1b + 2*cp);
    #pragma unroll
    for (int vo = 0; vo < 4; vo++){
      float4 a = cld4(CAVW + vo*4);
      ULL z = 0ULL;
      z = f2fma(ys[0], pkdup(a.x), z);
      z = f2fma(ys[1], pkdup(a.y), z);
      z = f2fma(ys[2], pkdup(a.z), z);
      z = f2fma(ys[3], pkdup(a.w), z);
      float2 f = up2(f2add(z, b1));
      sts2(sA + base + vo*85*ST, pk(fmaxf(f.x, 0.f), fmaxf(f.y, 0.f)));
    }
  }
}

// ---------------- fused 3-layer ST-GCN: one CTA per (n, hw) ----------------
__global__ __launch_bounds__(192, 2)
void stgcn_kernel(const float* __restrict__ x, float* __restrict__ out)
{
  __shared__ __align__(16) float sA[NODES*ST];   // 27.2 KB: activation rows only
  const int hw  = blockIdx.x;
  const int n   = blockIdx.y;
  const int tid = threadIdx.x;

  {
    const float* xb = x + ((size_t)n * NODES * 18) * HW + hw;
    for (int i = tid; i < NODES*18; i += 192){
      int nd = i / 18, c = i - nd*18;
      sA[nd*ST + c] = xb[(size_t)i * HW];
    }
  }
  __syncthreads();

  const bool act  = tid < 180;
  const int  g    = tid / 9;
  const int  j    = tid - g*9;
  const bool has2 = (j < 8);
  const int  v0   = 2*j;                  // j==8 -> 16
  const int  v1   = has2 ? v0 + 1 : v0;
  const int  nd0  = g*17 + v0, nd1 = g*17 + v1;

  ULL acc0[8], acc1[8];
  float xr0[18], xr1[18];

  if (act){
    #pragma unroll
    for (int c = 0; c < 18; c++){ xr0[c] = sA[nd0*ST + c]; xr1[c] = sA[nd1*ST + c]; }
    #pragma unroll
    for (int q = 0; q < 8; q++){ ULL ci = cld2(CCI + 2*q); acc0[q] = ci; acc1[q] = ci; }
  }
  __syncthreads();                 // x reads complete before A(0) overwrites rows
  if (act) phaseA<18>(CWG0, CBG, xr0, xr1, sA, nd0, nd1, has2);
  __syncthreads();

  #pragma unroll 1
  for (int L = 0; L < 3; L++){
    #pragma unroll 1
    for (int k = 0; k < 7; k++){
      // ---- phase B(k): in-place aggregation + BN1 + ReLU ----
      if (k < 4)      phaseBsp(L, k, sA, tid);
      else if (k < 6) phaseBtm(L, k, sA, tid);
      else            phaseBvw(L, sA, tid);
      __syncthreads();
      // ---- phase C(k) + phase A(next): both touch only thread-owned rows ----
      if (act){
        phaseC(CWT + (L*7 + k)*256, sA, nd0, nd1, acc0, acc1);
        if (k < 6){
          int wb = (L == 0) ? CWG0 + (k+1)*288 : (L == 1 ? CWG1 : CWG2) + (k+1)*256;
          int bb = CBG + (L*7 + k + 1)*16;
          if (L == 0) phaseA<18>(wb, bb, xr0, xr1, sA, nd0, nd1, has2);
          else        phaseA<16>(wb, bb, xr0, xr1, sA, nd0, nd1, has2);
        } else if (L < 2){
          // layer boundary: xr = relu(acc); acc = CI(next) + 7*xr (residual x7)
          const int cib = CCI + (L+1)*16;
          #pragma unroll
          for (int q = 0; q < 8; q++){
            float2 a = up2(acc0[q]), b = up2(acc1[q]);
            float xa0 = fmaxf(a.x, 0.f), xa1 = fmaxf(a.y, 0.f);
            float xb0 = fmaxf(b.x, 0.f), xb1 = fmaxf(b.y, 0.f);
            xr0[2*q] = xa0; xr0[2*q+1] = xa1;
            xr1[2*q] = xb0; xr1[2*q+1] = xb1;
            float ci0 = cP[cib + 2*q], ci1 = cP[cib + 2*q + 1];
            acc0[q] = pk(fmaf(7.f, xa0, ci0), fmaf(7.f, xa1, ci1));
            acc1[q] = pk(fmaf(7.f, xb0, ci0), fmaf(7.f, xb1, ci1));
          }
          int wb = (L == 0) ? CWG1 : CWG2;
          int bb = CBG + (L+1)*7*16;
          phaseA<16>(wb, bb, xr0, xr1, sA, nd0, nd1, has2);
        }
      }
      __syncthreads();
    }
  }

  // ---- final ReLU + output ----
  if (act){
    float* o0 = out + ((size_t)(n*NODES + nd0) * 16) * HW + hw;
    #pragma unroll
    for (int q = 0; q < 8; q++){
      float2 a = up2(acc0[q]);
      o0[(size_t)(2*q)     * HW] = fmaxf(a.x, 0.f);
      o0[(size_t)(2*q + 1) * HW] = fmaxf(a.y, 0.f);
    }
    if (has2){
      float* o1 = out + ((size_t)(n*NODES + nd1) * 16) * HW + hw;
      #pragma unroll
      for (int q = 0; q < 8; q++){
        float2 b = up2(acc1[q]);
        o1[(size_t)(2*q)     * HW] = fmaxf(b.x, 0.f);
        o1[(size_t)(2*q + 1) * HW] = fmaxf(b.y, 0.f);
      }
    }
  }
}

extern "C" void kernel_launch(void* const* d_in, const int* in_sizes, int n_in,
                              void* d_out, int out_size)
{
  (void)in_sizes; (void)n_in; (void)out_size;
  const float* x    = (const float*)d_in[0];
  const float* A_sp = (const float*)d_in[1];
  const float* A_tm = (const float*)d_in[2];
  const float* A_vw = (const float*)d_in[3];
  const float* Wg0  = (const float*)d_in[4];
  const float* bg0  = (const float*)d_in[5];
  const float* Wg   = (const float*)d_in[6];
  const float* bg   = (const float*)d_in[7];
  const float* bn1g = (const float*)d_in[8];
  const float* bn1b = (const float*)d_in[9];
  const float* Wt   = (const float*)d_in[10];
  const float* bt   = (const float*)d_in[11];
  const float* bn2g = (const float*)d_in[12];
  const float* bn2b = (const float*)d_in[13];

  prep_kernel<<<1, 256>>>(A_sp, A_tm, A_vw, Wg0, bg0, Wg, bg,
                          bn1g, bn1b, Wt, bt, bn2g, bn2b);

  void* sp = nullptr;
  cudaGetSymbolAddress(&sp, gS);
  cudaMemcpyToSymbolAsync(cP, sp, CTOT * sizeof(float), 0, cudaMemcpyDeviceToDevice);

  stgcn_kernel<<<dim3(HW, NB), 192>>>(x, (float*)d_out);
}

// round 5
// speedup vs baseline: 1.2641x; 1.2641x over previous
#include <cuda_runtime.h>
#include <cstddef>

typedef unsigned long long ULL;

#define EPSF 1e-5f
#define NB 8
#define HW 256
#define NODES 340      // 4 views * 5 T * 17 V
#define ST 20          // activation row stride (floats)

// ---- shared/global parameter table layout (floats) ----
#define CASP 0         // A_sp padded: 4*17 rows x 20  = 1360
#define CATM 1360      // A_tm padded: 2*5 rows x 8    = 80
#define CAVW 1440      // A_vw: 4x4                    = 16
#define CWG0 1456      // 7*18*16 [k][c][o], s1-folded = 2016
#define CWG1 3472      // 7*16*16                      = 1792
#define CWG2 5264      // 1792
#define CBG  7056      // 3*7*16, s1-folded            = 336
#define CB1  7392      // 336
#define CWT  7728      // 3*7*16*16 [l][k][c][o], s2-folded = 5376
#define CCI  13104     // 3*16: sum_k(bt*s2+b2)        = 48
#define CTOT 13152     // 52.6 KB (16B-aligned: 13152*4 = 52608)

#define SM_FLOATS (CTOT + NODES*ST)     // 19952
#define SM_BYTES  (SM_FLOATS * 4)       // 79808 B -> 2 CTAs/SM

__device__ float gS[CTOT];

// ---- packed-f32x2 helpers (Blackwell) ----
__device__ __forceinline__ ULL f2fma(ULL a, ULL b, ULL c){
  ULL d; asm("fma.rn.f32x2 %0,%1,%2,%3;" : "=l"(d) : "l"(a), "l"(b), "l"(c)); return d;
}
__device__ __forceinline__ ULL f2add(ULL a, ULL b){
  ULL d; asm("add.rn.f32x2 %0,%1,%2;" : "=l"(d) : "l"(a), "l"(b)); return d;
}
__device__ __forceinline__ ULL pkdup(float a){
  ULL d; asm("mov.b64 %0,{%1,%1};" : "=l"(d) : "f"(a), "f"(a)); return d;
}
__device__ __forceinline__ ULL pk(float a, float b){
  ULL d; asm("mov.b64 %0,{%1,%2};" : "=l"(d) : "f"(a), "f"(b)); return d;
}
__device__ __forceinline__ float2 up2(ULL a){
  float2 v; asm("mov.b64 {%0,%1},%2;" : "=f"(v.x), "=f"(v.y) : "l"(a)); return v;
}
__device__ __forceinline__ ULL lds2(const float* p){ return *reinterpret_cast<const ULL*>(p); }
__device__ __forceinline__ void sts2(float* p, ULL v){ *reinterpret_cast<ULL*>(p) = v; }
__device__ __forceinline__ float4 lds4(const float* p){ return *reinterpret_cast<const float4*>(p); }

// ---------------- prep: fold BN scales into weights, pad A, transpose ----------------
__global__ void prep_kernel(const float* __restrict__ A_sp, const float* __restrict__ A_tm,
                            const float* __restrict__ A_vw,
                            const float* __restrict__ Wg0, const float* __restrict__ bg0,
                            const float* __restrict__ Wg,  const float* __restrict__ bg,
                            const float* __restrict__ bn1g, const float* __restrict__ bn1b,
                            const float* __restrict__ Wt,  const float* __restrict__ bt,
                            const float* __restrict__ bn2g, const float* __restrict__ bn2b)
{
  const int t = threadIdx.x;
  const float inv = rsqrtf(1.f + EPSF);
  // A_sp padded rows of 20
  for (int i = t; i < 1360; i += 256){
    int k = i / 340, r = i % 340, u = r / 20, vp = r % 20;
    gS[CASP + i] = (vp < 17) ? A_sp[(k*17 + u)*17 + vp] : 0.f;
  }
  // A_tm padded rows of 8
  for (int i = t; i < 80; i += 256){
    int k = i / 40, r = i % 40, tt = r / 8, tp = r % 8;
    gS[CATM + i] = (tp < 5) ? A_tm[(k*5 + tt)*5 + tp] : 0.f;
  }
  for (int i = t; i < 16; i += 256) gS[CAVW + i] = A_vw[i];
  // Wg0: (7,16,18) [k][o][c] -> [k][c][o], * s1(layer0)
  for (int i = t; i < 2016; i += 256){
    int k = i / 288, r = i % 288, o = r / 18, c = r % 18;
    gS[CWG0 + (k*18 + c)*16 + o] = Wg0[i] * (bn1g[k*16 + o] * inv);
  }
  // Wg: (2,7,16,16) [l][k][o][c] -> per-layer [k][c][o], * s1(layer l+1)
  for (int i = t; i < 3584; i += 256){
    int l = i / 1792, r = i % 1792, k = r / 256, q = r % 256, o = q / 16, c = q % 16;
    gS[CWG1 + l*1792 + (k*16 + c)*16 + o] = Wg[i] * (bn1g[((l+1)*7 + k)*16 + o] * inv);
  }
  // bg (s1-folded) and b1
  for (int i = t; i < 336; i += 256){
    float bgv = (i < 112) ? bg0[i] : bg[i - 112];
    gS[CBG + i] = bgv * (bn1g[i] * inv);
    gS[CB1 + i] = bn1b[i];
  }
  // Wt: (3,7,16,16) [l][k][o][c] -> [l][k][c][o], * s2
  for (int i = t; i < 5376; i += 256){
    int l = i / 1792, r = i % 1792, k = r / 256, q = r % 256, o = q / 16, c = q % 16;
    gS[CWT + l*1792 + (k*16 + c)*16 + o] = Wt[i] * (bn2g[(l*7 + k)*16 + o] * inv);
  }
  // CI[l][o] = sum_k (bt*s2 + b2)
  for (int i = t; i < 48; i += 256){
    int l = i / 16, o = i % 16;
    float s = 0.f;
    for (int k = 0; k < 7; k++){
      int id = (l*7 + k)*16 + o;
      s += bt[id] * (bn2g[id] * inv) + bn2b[id];
    }
    gS[CCI + i] = s;
  }
}

// ---- phase A: conv1 (s1-folded weights from smem) -> y rows in sA ----
template<int CIN>
__device__ __forceinline__ void phaseA(const float* __restrict__ sP, int wb, int bb,
                                       const float (&xr0)[18], const float (&xr1)[18],
                                       float* sA, int nd0, int nd1, bool has2)
{
  ULL y0[8], y1[8];
  #pragma unroll
  for (int q = 0; q < 4; q++){
    ulonglong2 b = *reinterpret_cast<const ulonglong2*>(sP + bb + 4*q);
    y0[2*q] = b.x; y0[2*q+1] = b.y;
    y1[2*q] = b.x; y1[2*q+1] = b.y;
  }
  #pragma unroll
  for (int c = 0; c < CIN; c++){
    ULL xa = pkdup(xr0[c]), xb = pkdup(xr1[c]);
    #pragma unroll
    for (int q = 0; q < 4; q++){
      ulonglong2 w = *reinterpret_cast<const ulonglong2*>(sP + wb + c*16 + 4*q);
      y0[2*q]   = f2fma(w.x, xa, y0[2*q]);
      y0[2*q+1] = f2fma(w.y, xa, y0[2*q+1]);
      y1[2*q]   = f2fma(w.x, xb, y1[2*q]);
      y1[2*q+1] = f2fma(w.y, xb, y1[2*q+1]);
    }
  }
  ulonglong2* d0 = reinterpret_cast<ulonglong2*>(sA + nd0*ST);
  #pragma unroll
  for (int q = 0; q < 4; q++){ ulonglong2 t; t.x = y0[2*q]; t.y = y0[2*q+1]; d0[q] = t; }
  if (has2){
    ulonglong2* d1 = reinterpret_cast<ulonglong2*>(sA + nd1*ST);
    #pragma unroll
    for (int q = 0; q < 4; q++){ ulonglong2 t; t.x = y1[2*q]; t.y = y1[2*q+1]; d1[q] = t; }
  }
}

// ---- phase C: conv2 (s2-folded) accumulated straight into acc ----
__device__ __forceinline__ void phaseC(const float* __restrict__ sP, int wb,
                                       const float* sA, int nd0, int nd1,
                                       ULL (&acc0)[8], ULL (&acc1)[8])
{
  float4 ra[4], rb[4];
  #pragma unroll
  for (int q = 0; q < 4; q++){
    ra[q] = lds4(sA + nd0*ST + 4*q);
    rb[q] = lds4(sA + nd1*ST + 4*q);
  }
  #pragma unroll
  for (int q4 = 0; q4 < 4; q4++){
    const float av[4] = {ra[q4].x, ra[q4].y, ra[q4].z, ra[q4].w};
    const float bv[4] = {rb[q4].x, rb[q4].y, rb[q4].z, rb[q4].w};
    #pragma unroll
    for (int s = 0; s < 4; s++){
      int c = q4*4 + s;
      ULL xa = pkdup(av[s]), xb = pkdup(bv[s]);
      #pragma unroll
      for (int q = 0; q < 4; q++){
        ulonglong2 w = *reinterpret_cast<const ulonglong2*>(sP + wb + c*16 + 4*q);
        acc0[2*q]   = f2fma(w.x, xa, acc0[2*q]);
        acc0[2*q+1] = f2fma(w.y, xa, acc0[2*q+1]);
        acc1[2*q]   = f2fma(w.x, xb, acc1[2*q]);
        acc1[2*q+1] = f2fma(w.y, xb, acc1[2*q+1]);
      }
    }
  }
}

// ---- phase B spatial: per (group, ch-pair) slice, in-place A-mix + b1 + ReLU ----
__device__ __forceinline__ void phaseBsp(const float* __restrict__ sP, int L, int k,
                                         float* sA, int tid)
{
  if (tid >= 160) return;
  const int g = tid >> 3, cp = tid & 7;
  const int base = (g*17)*ST + 2*cp;
  ULL ys[20];
  #pragma unroll
  for (int v = 0; v < 17; v++) ys[v] = lds2(sA + base + v*ST);
  ys[17] = 0ULL; ys[18] = 0ULL; ys[19] = 0ULL;
  const ULL b1 = lds2(sP + CB1 + (L*7 + k)*16 + 2*cp);
  const int ab = CASP + k*340;
  #pragma unroll
  for (int u = 0; u < 17; u++){
    ULL z = 0ULL;
    #pragma unroll
    for (int q = 0; q < 5; q++){
      float4 a = lds4(sP + ab + u*20 + 4*q);
      z = f2fma(ys[4*q + 0], pkdup(a.x), z);
      z = f2fma(ys[4*q + 1], pkdup(a.y), z);
      z = f2fma(ys[4*q + 2], pkdup(a.z), z);
      z = f2fma(ys[4*q + 3], pkdup(a.w), z);
    }
    float2 f = up2(f2add(z, b1));
    sts2(sA + base + u*ST, pk(fmaxf(f.x, 0.f), fmaxf(f.y, 0.f)));
  }
}

// ---- phase B temporal ----
__device__ __forceinline__ void phaseBtm(const float* __restrict__ sP, int L, int k,
                                         float* sA, int tid)
{
  const int b1b = CB1 + (L*7 + k)*16;
  const int ab  = CATM + (k - 4)*40;
  for (int it = tid; it < 544; it += 192){
    int vw = it / 136; int r = it - vw*136; int v = r >> 3; int cp = r & 7;
    const int base = (vw*85 + v)*ST + 2*cp;   // node (vw*5+tp)*17+v, tp stride 17*ST
    ULL ys[5];
    #pragma unroll
    for (int tp = 0; tp < 5; tp++) ys[tp] = lds2(sA + base + tp*17*ST);
    const ULL b1 = lds2(sP + b1b + 2*cp);
    #pragma unroll
    for (int t = 0; t < 5; t++){
      float4 a0 = lds4(sP + ab + t*8);
      float  a4 = sP[ab + t*8 + 4];
      ULL z = 0ULL;
      z = f2fma(ys[0], pkdup(a0.x), z);
      z = f2fma(ys[1], pkdup(a0.y), z);
      z = f2fma(ys[2], pkdup(a0.z), z);
      z = f2fma(ys[3], pkdup(a0.w), z);
      z = f2fma(ys[4], pkdup(a4),   z);
      float2 f = up2(f2add(z, b1));
      sts2(sA + base + t*17*ST, pk(fmaxf(f.x, 0.f), fmaxf(f.y, 0.f)));
    }
  }
}

// ---- phase B views ----
__device__ __forceinline__ void phaseBvw(const float* __restrict__ sP, int L,
                                         float* sA, int tid)
{
  const int b1b = CB1 + (L*7 + 6)*16;
  for (int it = tid; it < 680; it += 192){
    int t = it / 136; int r = it - t*136; int v = r >> 3; int cp = r & 7;
    const int base = (t*17 + v)*ST + 2*cp;    // node (vw*85 + t*17 + v), vw stride 85*ST
    ULL ys[4];
    #pragma unroll
    for (int vw = 0; vw < 4; vw++) ys[vw] = lds2(sA + base + vw*85*ST);
    const ULL b1 = lds2(sP + b1b + 2*cp);
    #pragma unroll
    for (int vo = 0; vo < 4; vo++){
      float4 a = lds4(sP + CAVW + vo*4);
      ULL z = 0ULL;
      z = f2fma(ys[0], pkdup(a.x), z);
      z = f2fma(ys[1], pkdup(a.y), z);
      z = f2fma(ys[2], pkdup(a.z), z);
      z = f2fma(ys[3], pkdup(a.w), z);
      float2 f = up2(f2add(z, b1));
      sts2(sA + base + vo*85*ST, pk(fmaxf(f.x, 0.f), fmaxf(f.y, 0.f)));
    }
  }
}

// ---------------- fused 3-layer ST-GCN: one CTA per (n, hw) ----------------
__global__ __launch_bounds__(192, 2)
void stgcn_kernel(const float* __restrict__ x, float* __restrict__ out)
{
  extern __shared__ __align__(16) float smf[];
  float* sP = smf;           // 13152 floats of parameters
  float* sA = smf + CTOT;    // 340 rows x stride 20

  const int hw  = blockIdx.x;
  const int n   = blockIdx.y;
  const int tid = threadIdx.x;

  // stage parameters (L2-resident after first wave) and input slice
  for (int i = tid*4; i < CTOT; i += 192*4)
    *reinterpret_cast<float4*>(sP + i) = *reinterpret_cast<const float4*>(gS + i);
  {
    const float* xb = x + ((size_t)n * NODES * 18) * HW + hw;
    for (int i = tid; i < NODES*18; i += 192){
      int nd = i / 18, c = i - nd*18;
      sA[nd*ST + c] = xb[(size_t)i * HW];
    }
  }
  __syncthreads();

  const bool act  = tid < 180;
  const int  g    = tid / 9;
  const int  j    = tid - g*9;
  const bool has2 = (j < 8);
  const int  v0   = 2*j;                  // j==8 -> 16
  const int  v1   = has2 ? v0 + 1 : v0;
  const int  nd0  = g*17 + v0, nd1 = g*17 + v1;

  ULL acc0[8], acc1[8];
  float xr0[18], xr1[18];

  if (act){
    #pragma unroll
    for (int c = 0; c < 18; c++){ xr0[c] = sA[nd0*ST + c]; xr1[c] = sA[nd1*ST + c]; }
    #pragma unroll
    for (int q = 0; q < 8; q++){ ULL ci = lds2(sP + CCI + 2*q); acc0[q] = ci; acc1[q] = ci; }
  }
  __syncthreads();                 // x reads complete before A(0) overwrites rows
  if (act) phaseA<18>(sP, CWG0, CBG, xr0, xr1, sA, nd0, nd1, has2);
  __syncthreads();

  #pragma unroll 1
  for (int L = 0; L < 3; L++){
    #pragma unroll 1
    for (int k = 0; k < 7; k++){
      // ---- phase B(k): in-place aggregation + BN1 + ReLU ----
      if (k < 4)      phaseBsp(sP, L, k, sA, tid);
      else if (k < 6) phaseBtm(sP, L, k, sA, tid);
      else            phaseBvw(sP, L, sA, tid);
      __syncthreads();
      // ---- phase C(k) + phase A(next): both touch only thread-owned rows ----
      if (act){
        phaseC(sP, CWT + (L*7 + k)*256, sA, nd0, nd1, acc0, acc1);
        if (k < 6){
          int wb = (L == 0) ? CWG0 + (k+1)*288 : (L == 1 ? CWG1 : CWG2) + (k+1)*256;
          int bb = CBG + (L*7 + k + 1)*16;
          if (L == 0) phaseA<18>(sP, wb, bb, xr0, xr1, sA, nd0, nd1, has2);
          else        phaseA<16>(sP, wb, bb, xr0, xr1, sA, nd0, nd1, has2);
        } else if (L < 2){
          // layer boundary: xr = relu(acc); acc = CI(next) + 7*xr (residual x7)
          const int cib = CCI + (L+1)*16;
          #pragma unroll
          for (int q = 0; q < 8; q++){
            float2 a = up2(acc0[q]), b = up2(acc1[q]);
            float xa0 = fmaxf(a.x, 0.f), xa1 = fmaxf(a.y, 0.f);
            float xb0 = fmaxf(b.x, 0.f), xb1 = fmaxf(b.y, 0.f);
            xr0[2*q] = xa0; xr0[2*q+1] = xa1;
            xr1[2*q] = xb0; xr1[2*q+1] = xb1;
            float ci0 = sP[cib + 2*q], ci1 = sP[cib + 2*q + 1];
            acc0[q] = pk(fmaf(7.f, xa0, ci0), fmaf(7.f, xa1, ci1));
            acc1[q] = pk(fmaf(7.f, xb0, ci0), fmaf(7.f, xb1, ci1));
          }
          int wb = (L == 0) ? CWG1 : CWG2;
          int bb = CBG + (L+1)*7*16;
          phaseA<16>(sP, wb, bb, xr0, xr1, sA, nd0, nd1, has2);
        }
      }
      __syncthreads();
    }
  }

  // ---- final ReLU + output ----
  if (act){
    float* o0 = out + ((size_t)(n*NODES + nd0) * 16) * HW + hw;
    #pragma unroll
    for (int q = 0; q < 8; q++){
      float2 a = up2(acc0[q]);
      o0[(size_t)(2*q)     * HW] = fmaxf(a.x, 0.f);
      o0[(size_t)(2*q + 1) * HW] = fmaxf(a.y, 0.f);
    }
    if (has2){
      float* o1 = out + ((size_t)(n*NODES + nd1) * 16) * HW + hw;
      #pragma unroll
      for (int q = 0; q < 8; q++){
        float2 b = up2(acc1[q]);
        o1[(size_t)(2*q)     * HW] = fmaxf(b.x, 0.f);
        o1[(size_t)(2*q + 1) * HW] = fmaxf(b.y, 0.f);
      }
    }
  }
}

extern "C" void kernel_launch(void* const* d_in, const int* in_sizes, int n_in,
                              void* d_out, int out_size)
{
  (void)in_sizes; (void)n_in; (void)out_size;
  const float* x    = (const float*)d_in[0];
  const float* A_sp = (const float*)d_in[1];
  const float* A_tm = (const float*)d_in[2];
  const float* A_vw = (const float*)d_in[3];
  const float* Wg0  = (const float*)d_in[4];
  const float* bg0  = (const float*)d_in[5];
  const float* Wg   = (const float*)d_in[6];
  const float* bg   = (const float*)d_in[7];
  const float* bn1g = (const float*)d_in[8];
  const float* bn1b = (const float*)d_in[9];
  const float* Wt   = (const float*)d_in[10];
  const float* bt   = (const float*)d_in[11];
  const float* bn2g = (const float*)d_in[12];
  const float* bn2b = (const float*)d_in[13];

  cudaFuncSetAttribute(stgcn_kernel, cudaFuncAttributeMaxDynamicSharedMemorySize, SM_BYTES);

  prep_kernel<<<1, 256>>>(A_sp, A_tm, A_vw, Wg0, bg0, Wg, bg,
                          bn1g, bn1b, Wt, bt, bn2g, bn2b);
  stgcn_kernel<<<dim3(HW, NB), 192, SM_BYTES>>>(x, (float*)d_out);
}